// round 13
// baseline (speedup 1.0000x reference)
#include <cuda_runtime.h>
#include <cuda_fp16.h>
#include <stdint.h>
#include <math.h>

#define MAXN 100000
#define MAXE 1600000
#define MAXB 1024

// ---------------- scratch (static device globals; no allocation) -------------
__device__ int    g_deg[MAXN];
__device__ float  g_dinv[MAXN];
__device__ int    g_rowptr[MAXN + 1];
__device__ int    g_fill[MAXN];
__device__ uint2  g_csr[MAXE];                 // packed {src, norm_bits}
__device__ __half g_xh[(size_t)MAXN * 64];     // fp16 input features
__device__ __half g_ha[(size_t)MAXN * 128];    // fp16 hidden ping
__device__ __half g_hb[(size_t)MAXN * 128];    // fp16 hidden pong
__device__ __half g_wt1[64 * 128];             // W1^T fp16 [n][k]
__device__ __half g_wt2[128 * 128];
__device__ __half g_wt3[128 * 128];
__device__ __half g_wt4[128 * 128];
__device__ int    g_bsum[1024];
__device__ float  g_xcat[MAXB * 384];
__device__ float  g_t1[MAXB * 256];
__device__ float  g_f1[MAXB * 256];
__device__ float  g_f2[MAXB * 128];

// ---------------- prep: x->fp16, W->fp16 transposed, zero deg/fill -----------
__global__ void prep_kernel(const float* __restrict__ x, int n,
                            const float* __restrict__ W1, const float* __restrict__ W2,
                            const float* __restrict__ W3, const float* __restrict__ W4) {
    int i = blockIdx.x * blockDim.x + threadIdx.x;
    int total = n * 64;
    if (i < total) g_xh[i] = __float2half(x[i]);
    if (i < n) { g_deg[i] = 0; g_fill[i] = 0; }
    if (i < 8192) {                       // W1: K=64
        int nr = i >> 6, k = i & 63;
        g_wt1[nr * 64 + k] = __float2half(W1[k * 128 + nr]);
    } else if (i < 8192 + 16384) {
        int j = i - 8192; int nr = j >> 7, k = j & 127;
        g_wt2[nr * 128 + k] = __float2half(W2[k * 128 + nr]);
    } else if (i < 8192 + 2 * 16384) {
        int j = i - 8192 - 16384; int nr = j >> 7, k = j & 127;
        g_wt3[nr * 128 + k] = __float2half(W3[k * 128 + nr]);
    } else if (i < 8192 + 3 * 16384) {
        int j = i - 8192 - 2 * 16384; int nr = j >> 7, k = j & 127;
        g_wt4[nr * 128 + k] = __float2half(W4[k * 128 + nr]);
    }
}

__global__ void hist_kernel(const int* __restrict__ dst, int E) {
    int i = blockIdx.x * blockDim.x + threadIdx.x;
    if (i < E) atomicAdd(&g_deg[dst[i]], 1);
}

// block sums of deg (1024 per block) + fused dinv
__global__ void scan1_kernel(int n) {
    __shared__ int s[1024];
    int t = threadIdx.x;
    int i = blockIdx.x * 1024 + t;
    int v = (i < n) ? g_deg[i] : 0;
    if (i < n) g_dinv[i] = rsqrtf((float)(v + 2));
    s[t] = v;
    __syncthreads();
    for (int off = 512; off > 0; off >>= 1) {
        if (t < off) s[t] += s[t + off];
        __syncthreads();
    }
    if (t == 0) g_bsum[blockIdx.x] = s[0];
}

// merged scan2+scan3: each block redundantly reduces bsum[0..blk) for its base
__global__ void scan23_kernel(int n, int nsb) {
    __shared__ int s[1024];
    __shared__ int sb[1024];
    int t = threadIdx.x;
    int i = blockIdx.x * 1024 + t;
    sb[t] = (t < blockIdx.x) ? g_bsum[t] : 0;
    int v = (i < n) ? g_deg[i] : 0;
    s[t] = v;
    __syncthreads();
    for (int off = 512; off > 0; off >>= 1) {
        if (t < off) sb[t] += sb[t + off];
        __syncthreads();
    }
    int base = sb[0];
    for (int off = 1; off < 1024; off <<= 1) {
        int a = (t >= off) ? s[t - off] : 0;
        __syncthreads();
        s[t] += a;
        __syncthreads();
    }
    int incl = s[t];
    if (i < n) {
        g_rowptr[i] = base + incl - v;
        if (i == n - 1) g_rowptr[n] = base + incl;
    }
}

__global__ void csrfill_kernel(const int* __restrict__ src, const int* __restrict__ dst, int E) {
    int i = blockIdx.x * blockDim.x + threadIdx.x;
    if (i >= E) return;
    int d = dst[i];
    int sidx = src[i];
    int p = g_rowptr[d] + atomicAdd(&g_fill[d], 1);
    g_csr[p] = make_uint2((unsigned)sidx,
                          __float_as_uint(g_dinv[sidx] * g_dinv[d]));
}

// ---------------- fp16 mma + cp.async helpers ---------------------------------
__device__ __forceinline__ void ldmx4(uint32_t r[4], const __half* p) {
    uint32_t addr = (uint32_t)__cvta_generic_to_shared(p);
    asm volatile("ldmatrix.sync.aligned.m8n8.x4.shared.b16 {%0,%1,%2,%3}, [%4];"
        : "=r"(r[0]), "=r"(r[1]), "=r"(r[2]), "=r"(r[3]) : "r"(addr));
}
__device__ __forceinline__ void ldmx2(uint32_t r[2], const __half* p) {
    uint32_t addr = (uint32_t)__cvta_generic_to_shared(p);
    asm volatile("ldmatrix.sync.aligned.m8n8.x2.shared.b16 {%0,%1}, [%2];"
        : "=r"(r[0]), "=r"(r[1]) : "r"(addr));
}
__device__ __forceinline__ void mma_f16(float d[4], const uint32_t a[4], const uint32_t b[2]) {
    asm volatile("mma.sync.aligned.m16n8k16.row.col.f32.f16.f16.f32 "
        "{%0,%1,%2,%3}, {%4,%5,%6,%7}, {%8,%9}, {%0,%1,%2,%3};"
        : "+f"(d[0]), "+f"(d[1]), "+f"(d[2]), "+f"(d[3])
        : "r"(a[0]), "r"(a[1]), "r"(a[2]), "r"(a[3]), "r"(b[0]), "r"(b[1]));
}
template <int BYTES>
__device__ __forceinline__ void cp_async_b(uint32_t saddr, const void* g) {
    asm volatile("cp.async.ca.shared.global [%0], [%1], %2;"
        :: "r"(saddr), "l"(g), "n"(BYTES));
}
__device__ __forceinline__ void cp_commit() {
    asm volatile("cp.async.commit_group;");
}
template <int N>
__device__ __forceinline__ void cp_wait() {
    asm volatile("cp.async.wait_group %0;" :: "n"(N));
}

// ---------------- fused GCN layer: cp.async-staged gather + fp16 MMA ----------
// block = 512 threads; tile = 128 nodes (8/warp); H[128x128] = relu(Agg(X)*W + b)
// gather: per-warp S-stage smem ring; edge rows flow via cp.async (no reg chain)
template <int DIN>
__global__ __launch_bounds__(512, 2)
void gcn_layer_kernel(const __half* __restrict__ X, const __half* __restrict__ WT,
                      const float* __restrict__ bias, __half* __restrict__ H, int M) {
    constexpr int AS = DIN + 8;          // half stride -> conflict-free ldmatrix
    constexpr int HPL = DIN / 32;        // halves per lane (2 or 4)
    constexpr int S = 8;                 // ring stages per warp
    extern __shared__ __half smh[];
    __half* Asm = smh;                   // [128][AS]
    __half* Bsm = smh + 128 * AS;        // [128][AS] (n-major, k contiguous)
    __half* ring = smh + 2 * 128 * AS;   // [16 warps][S][DIN]
    int tid = threadIdx.x, warp = tid >> 5, lane = tid & 31;
    int m0 = blockIdx.x * 128;

    // ---- load W^T (fp16, [n][k]) into smem: 16B vector copies ----
    constexpr int V8 = DIN / 8;
    for (int i = tid; i < 128 * V8; i += 512) {
        int nr = i / V8;
        int kv = (i - nr * V8) * 8;
        *(uint4*)&Bsm[nr * AS + kv] = *(const uint4*)&WT[nr * DIN + kv];
    }

    // ---- phase A: gather-aggregate 8 nodes/warp via cp.async ring ----
    __half* wring = ring + warp * (S * DIN);
    uint32_t rlane = (uint32_t)__cvta_generic_to_shared(wring) + lane * (HPL * 2);
    for (int i = 0; i < 8; i++) {
        int nl = warp * 8 + i;
        int node = m0 + nl;
        float acc[HPL];
#pragma unroll
        for (int j = 0; j < HPL; j++) acc[j] = 0.f;
        if (node < M) {
            float di = g_dinv[node];
            float w0 = 2.f * di * di;    // two self-loops
            const __half* xrow = X + (size_t)node * DIN + lane * HPL;
            if constexpr (HPL == 4) {
                uint2 u = *(const uint2*)xrow;
                float2 f0 = __half22float2(*(__half2*)&u.x);
                float2 f1 = __half22float2(*(__half2*)&u.y);
                acc[0] = w0 * f0.x; acc[1] = w0 * f0.y;
                acc[2] = w0 * f1.x; acc[3] = w0 * f1.y;
            } else {
                float2 f0 = __half22float2(*(const __half2*)xrow);
                acc[0] = w0 * f0.x; acc[1] = w0 * f0.y;
            }
            int e0 = g_rowptr[node];
            int deg = g_rowptr[node + 1] - e0;
            // prologue: ALWAYS commit S groups (empties pad low-degree nodes)
#pragma unroll
            for (int s = 0; s < S; s++) {
                if (s < deg) {
                    unsigned sn = g_csr[e0 + s].x;
                    cp_async_b<HPL * 2>(rlane + s * (DIN * 2),
                                        X + (size_t)sn * DIN + lane * HPL);
                }
                cp_commit();
            }
            // steady state: one issue (or empty) + one consume per edge
            for (int t = 0; t < deg; t++) {
                int f = t + S;
                if (f < deg) {
                    unsigned sn = g_csr[e0 + f].x;
                    cp_async_b<HPL * 2>(rlane + (f & (S - 1)) * (DIN * 2),
                                        X + (size_t)sn * DIN + lane * HPL);
                }
                cp_commit();
                cp_wait<S - 1>();                    // stage t now resident
                float nm = __uint_as_float(g_csr[e0 + t].y);   // L1-hot reload
                const __half* st = wring + (t & (S - 1)) * DIN + lane * HPL;
                if constexpr (HPL == 4) {
                    uint2 u = *(const uint2*)st;
                    float2 a0 = __half22float2(*(__half2*)&u.x);
                    float2 a1 = __half22float2(*(__half2*)&u.y);
                    acc[0] = fmaf(nm, a0.x, acc[0]); acc[1] = fmaf(nm, a0.y, acc[1]);
                    acc[2] = fmaf(nm, a1.x, acc[2]); acc[3] = fmaf(nm, a1.y, acc[3]);
                } else {
                    float2 a0 = __half22float2(*(const __half2*)st);
                    acc[0] = fmaf(nm, a0.x, acc[0]); acc[1] = fmaf(nm, a0.y, acc[1]);
                }
            }
        }
        if constexpr (HPL == 4) {
            __half2 h0 = __floats2half2_rn(acc[0], acc[1]);
            __half2 h1 = __floats2half2_rn(acc[2], acc[3]);
            uint2 pk;
            pk.x = *(uint32_t*)&h0; pk.y = *(uint32_t*)&h1;
            *(uint2*)&Asm[nl * AS + lane * 4] = pk;
        } else {
            __half2 h0 = __floats2half2_rn(acc[0], acc[1]);
            *(uint32_t*)&Asm[nl * AS + lane * 2] = *(uint32_t*)&h0;
        }
    }
    __syncthreads();

    // ---- phase B: fp16 MMA from smem, no barriers in k-loop ----
    int wm = (warp >> 2) * 32;
    int wn = (warp & 3) * 32;
    float acc[2][4][4];
#pragma unroll
    for (int mi = 0; mi < 2; mi++)
#pragma unroll
        for (int ni = 0; ni < 4; ni++)
#pragma unroll
            for (int r = 0; r < 4; r++) acc[mi][ni][r] = 0.f;

    int l16 = lane & 15;
#pragma unroll
    for (int kk = 0; kk < DIN; kk += 16) {
        uint32_t a[2][4];
#pragma unroll
        for (int mi = 0; mi < 2; mi++)
            ldmx4(a[mi], &Asm[(wm + mi * 16 + l16) * AS + kk + (lane >> 4) * 8]);
        uint32_t b[4][2];
#pragma unroll
        for (int ni = 0; ni < 4; ni++)
            ldmx2(b[ni], &Bsm[(wn + ni * 8 + (l16 & 7)) * AS + kk + (l16 >> 3) * 8]);
#pragma unroll
        for (int mi = 0; mi < 2; mi++)
#pragma unroll
            for (int ni = 0; ni < 4; ni++)
                mma_f16(acc[mi][ni], a[mi], b[ni]);
    }

    // ---- epilogue: bias + relu -> fp16 ----
    int ar = lane >> 2, ac = lane & 3;
#pragma unroll
    for (int mi = 0; mi < 2; mi++) {
        int row = m0 + wm + mi * 16 + ar;
#pragma unroll
        for (int ni = 0; ni < 4; ni++) {
            int col = wn + ni * 8 + 2 * ac;
            float2 bb = *(const float2*)(bias + col);
            if (row < M) {
                __half2 o = __floats2half2_rn(fmaxf(acc[mi][ni][0] + bb.x, 0.f),
                                              fmaxf(acc[mi][ni][1] + bb.y, 0.f));
                *(__half2*)(H + (size_t)row * 128 + col) = o;
            }
            if (row + 8 < M) {
                __half2 o = __floats2half2_rn(fmaxf(acc[mi][ni][2] + bb.x, 0.f),
                                              fmaxf(acc[mi][ni][3] + bb.y, 0.f));
                *(__half2*)(H + (size_t)(row + 8) * 128 + col) = o;
            }
        }
    }
}

// ---------------- pooling (segment bounds via binary search) ------------------
__device__ __forceinline__ int lbound(const int* __restrict__ b, int n, int v) {
    int lo = 0, hi = n;
    while (lo < hi) {
        int mid = (lo + hi) >> 1;
        if (b[mid] < v) lo = mid + 1; else hi = mid;
    }
    return lo;
}

__global__ void pool_kernel(const __half* __restrict__ h,
                            const int* __restrict__ batch, int n) {
    int g = blockIdx.x;
    int c = threadIdx.x;
    int s = lbound(batch, n, g);
    int e = lbound(batch, n, g + 1);
    float sum = 0.f, mx = 0.f;   // h >= 0 after relu
    for (int i = s; i < e; i++) {
        float v = __half2float(h[(size_t)i * 128 + c]);
        sum += v;
        mx = fmaxf(mx, v);
    }
    float cnt = (float)(e - s);
    if (cnt < 1.f) cnt = 1.f;
    g_xcat[g * 384 + c]       = sum / cnt;
    g_xcat[g * 384 + 128 + c] = mx;
}

// ---------------- tiled MLP: 16 rows/block, B streamed once per block ---------
template <int N>
__global__ void mlp_tiled(const float* __restrict__ A, int lda,
                          const float* __restrict__ B,
                          const float* __restrict__ bias,
                          float* __restrict__ C, int ldc,
                          int M, int K) {
    __shared__ float As[16][33];
    int n = threadIdx.x;
    int m0 = blockIdx.x * 16;
    float acc[16];
    float bv = bias[n];
#pragma unroll
    for (int r = 0; r < 16; r++) acc[r] = bv;

    for (int k0 = 0; k0 < K; k0 += 32) {
        for (int i = threadIdx.x; i < 16 * 32; i += N) {
            int r = i >> 5, kk = i & 31;
            int gm = m0 + r, gk = k0 + kk;
            As[r][kk] = (gm < M && gk < K) ? A[(size_t)gm * lda + gk] : 0.f;
        }
        __syncthreads();
        int kmax = (K - k0 < 32) ? (K - k0) : 32;
        for (int kk = 0; kk < kmax; kk++) {
            float b = B[(size_t)(k0 + kk) * N + n];
#pragma unroll
            for (int r = 0; r < 16; r++)
                acc[r] = fmaf(As[r][kk], b, acc[r]);
        }
        __syncthreads();
    }
#pragma unroll
    for (int r = 0; r < 16; r++) {
        int gm = m0 + r;
        if (gm < M) C[(size_t)gm * ldc + n] = fmaxf(acc[r], 0.f);
    }
}

__global__ void final_kernel(const float* __restrict__ A, const float* __restrict__ W,
                             const float* __restrict__ b, float* __restrict__ out, int M) {
    int gw   = (blockIdx.x * blockDim.x + threadIdx.x) >> 5;
    int lane = threadIdx.x & 31;
    if (gw >= M) return;
    float s = 0.f;
    for (int k = lane; k < 128; k += 32)
        s = fmaf(A[(size_t)gw * 128 + k], W[k], s);
    for (int o = 16; o; o >>= 1) s += __shfl_xor_sync(0xffffffffu, s, o);
    if (lane == 0) out[gw] = 1.f / (1.f + expf(-(s + b[0])));
}

// ---------------- launch ------------------------------------------------------
extern "C" void kernel_launch(void* const* d_in, const int* in_sizes, int n_in,
                              void* d_out, int out_size) {
    const float* x_graph = (const float*)d_in[0];
    const int*   ei      = (const int*)d_in[1];
    const int*   batch   = (const int*)d_in[2];
    const float* x_tab   = (const float*)d_in[3];
    const float* Wg1 = (const float*)d_in[4];  const float* bg1 = (const float*)d_in[5];
    const float* Wg2 = (const float*)d_in[6];  const float* bg2 = (const float*)d_in[7];
    const float* Wg3 = (const float*)d_in[8];  const float* bg3 = (const float*)d_in[9];
    const float* Wg4 = (const float*)d_in[10]; const float* bg4 = (const float*)d_in[11];
    const float* Wt1 = (const float*)d_in[12]; const float* bt1 = (const float*)d_in[13];
    const float* Wt2 = (const float*)d_in[14]; const float* bt2 = (const float*)d_in[15];
    const float* Wf1 = (const float*)d_in[16]; const float* bf1 = (const float*)d_in[17];
    const float* Wf2 = (const float*)d_in[18]; const float* bf2 = (const float*)d_in[19];
    const float* Wf3 = (const float*)d_in[20]; const float* bf3 = (const float*)d_in[21];
    float* out = (float*)d_out;

    int n  = in_sizes[0] / 64;    // nodes
    int E  = in_sizes[1] / 2;     // edges
    int nb = in_sizes[3] / 200;   // graphs

    const int* src = ei;
    const int* dst = ei + E;

    __half *xhp, *hap, *hbp, *wt1p, *wt2p, *wt3p, *wt4p;
    float *xcatp, *t1p, *f1p, *f2p;
    cudaGetSymbolAddress((void**)&xhp,   g_xh);
    cudaGetSymbolAddress((void**)&hap,   g_ha);
    cudaGetSymbolAddress((void**)&hbp,   g_hb);
    cudaGetSymbolAddress((void**)&wt1p,  g_wt1);
    cudaGetSymbolAddress((void**)&wt2p,  g_wt2);
    cudaGetSymbolAddress((void**)&wt3p,  g_wt3);
    cudaGetSymbolAddress((void**)&wt4p,  g_wt4);
    cudaGetSymbolAddress((void**)&xcatp, g_xcat);
    cudaGetSymbolAddress((void**)&t1p,   g_t1);
    cudaGetSymbolAddress((void**)&f1p,   g_f1);
    cudaGetSymbolAddress((void**)&f2p,   g_f2);

    // dynamic smem: A + B tiles + per-warp cp.async ring (16 warps x 8 stages)
    int smem128 = (2 * 128 * (128 + 8) + 16 * 8 * 128) * 2;   // 102,400 B
    int smem64  = (2 * 128 * (64 + 8)  + 16 * 8 * 64)  * 2;   // 53,248 B
    cudaFuncSetAttribute(gcn_layer_kernel<128>, cudaFuncAttributeMaxDynamicSharedMemorySize, smem128);
    cudaFuncSetAttribute(gcn_layer_kernel<64>,  cudaFuncAttributeMaxDynamicSharedMemorySize, smem64);

    int tb = 256;
    int nBlocksE = (E + tb - 1) / tb;
    int nsb = (n + 1023) / 1024;
    int layerBlocks = (n + 127) / 128;
    int mlpBlocks = (nb + 15) / 16;

    // ---- prep + degree/CSR ----
    prep_kernel<<<(n * 64 + tb - 1) / tb, tb>>>(x_graph, n, Wg1, Wg2, Wg3, Wg4);
    hist_kernel<<<nBlocksE, tb>>>(dst, E);
    scan1_kernel<<<nsb, 1024>>>(n);
    scan23_kernel<<<nsb, 1024>>>(n, nsb);
    csrfill_kernel<<<nBlocksE, tb>>>(src, dst, E);

    // ---- fused GCN layers ----
    gcn_layer_kernel<64><<<layerBlocks, 512, smem64>>>(xhp, wt1p, bg1, hap, n);
    gcn_layer_kernel<128><<<layerBlocks, 512, smem128>>>(hap, wt2p, bg2, hbp, n);
    gcn_layer_kernel<128><<<layerBlocks, 512, smem128>>>(hbp, wt3p, bg3, hap, n);
    gcn_layer_kernel<128><<<layerBlocks, 512, smem128>>>(hap, wt4p, bg4, hbp, n);

    // ---- pooling (binary-search segments) ----
    pool_kernel<<<nb, 128>>>(hbp, batch, n);

    // ---- tabular branch (tiled MLPs) ----
    mlp_tiled<256><<<mlpBlocks, 256>>>(x_tab, 200, Wt1, bt1, t1p, 256, nb, 200);
    mlp_tiled<128><<<mlpBlocks, 128>>>(t1p, 256, Wt2, bt2, xcatp + 256, 384, nb, 256);

    // ---- fused head ----
    mlp_tiled<256><<<mlpBlocks, 256>>>(xcatp, 384, Wf1, bf1, f1p, 256, nb, 384);
    mlp_tiled<128><<<mlpBlocks, 128>>>(f1p, 256, Wf2, bf2, f2p, 128, nb, 256);
    final_kernel<<<(nb * 32 + tb - 1) / tb, tb>>>(f2p, Wf3, bf3, out, nb);
}

// round 14
// speedup vs baseline: 1.1687x; 1.1687x over previous
#include <cuda_runtime.h>
#include <cuda_fp16.h>
#include <stdint.h>
#include <math.h>

#define MAXN 100000
#define MAXE 1600000
#define MAXB 1024

// ---------------- scratch (static device globals; no allocation) -------------
__device__ int    g_deg[MAXN];
__device__ float  g_dinv[MAXN];
__device__ int    g_rowptr[MAXN + 1];
__device__ int    g_fill[MAXN];
__device__ uint2  g_csr[MAXE];                 // packed {src, norm_bits}
__device__ __half g_xh[(size_t)MAXN * 64];     // fp16 input features
__device__ __half g_ha[(size_t)MAXN * 128];    // fp16 hidden ping
__device__ __half g_hb[(size_t)MAXN * 128];    // fp16 hidden pong
__device__ __half g_wt1[64 * 128];             // W1^T fp16 [n][k]
__device__ __half g_wt2[128 * 128];
__device__ __half g_wt3[128 * 128];
__device__ __half g_wt4[128 * 128];
__device__ int    g_bsum[1024];
__device__ float  g_xcat[MAXB * 384];
__device__ float  g_t1[MAXB * 256];
__device__ float  g_f1[MAXB * 256];
__device__ float  g_f2[MAXB * 128];

// ---------------- prep: x->fp16, W->fp16 transposed, zero deg/fill -----------
__global__ void prep_kernel(const float* __restrict__ x, int n,
                            const float* __restrict__ W1, const float* __restrict__ W2,
                            const float* __restrict__ W3, const float* __restrict__ W4) {
    int i = blockIdx.x * blockDim.x + threadIdx.x;
    int total = n * 64;
    if (i < total) g_xh[i] = __float2half(x[i]);
    if (i < n) { g_deg[i] = 0; g_fill[i] = 0; }
    if (i < 8192) {                       // W1: K=64
        int nr = i >> 6, k = i & 63;
        g_wt1[nr * 64 + k] = __float2half(W1[k * 128 + nr]);
    } else if (i < 8192 + 16384) {
        int j = i - 8192; int nr = j >> 7, k = j & 127;
        g_wt2[nr * 128 + k] = __float2half(W2[k * 128 + nr]);
    } else if (i < 8192 + 2 * 16384) {
        int j = i - 8192 - 16384; int nr = j >> 7, k = j & 127;
        g_wt3[nr * 128 + k] = __float2half(W3[k * 128 + nr]);
    } else if (i < 8192 + 3 * 16384) {
        int j = i - 8192 - 2 * 16384; int nr = j >> 7, k = j & 127;
        g_wt4[nr * 128 + k] = __float2half(W4[k * 128 + nr]);
    }
}

__global__ void hist_kernel(const int* __restrict__ dst, int E) {
    int i = blockIdx.x * blockDim.x + threadIdx.x;
    if (i < E) atomicAdd(&g_deg[dst[i]], 1);
}

// block sums of deg (1024 per block) + fused dinv
__global__ void scan1_kernel(int n) {
    __shared__ int s[1024];
    int t = threadIdx.x;
    int i = blockIdx.x * 1024 + t;
    int v = (i < n) ? g_deg[i] : 0;
    if (i < n) g_dinv[i] = rsqrtf((float)(v + 2));
    s[t] = v;
    __syncthreads();
    for (int off = 512; off > 0; off >>= 1) {
        if (t < off) s[t] += s[t + off];
        __syncthreads();
    }
    if (t == 0) g_bsum[blockIdx.x] = s[0];
}

// merged scan2+scan3: each block redundantly reduces bsum[0..blk) for its base
__global__ void scan23_kernel(int n, int nsb) {
    __shared__ int s[1024];
    __shared__ int sb[1024];
    int t = threadIdx.x;
    int i = blockIdx.x * 1024 + t;
    sb[t] = (t < blockIdx.x) ? g_bsum[t] : 0;
    int v = (i < n) ? g_deg[i] : 0;
    s[t] = v;
    __syncthreads();
    for (int off = 512; off > 0; off >>= 1) {
        if (t < off) sb[t] += sb[t + off];
        __syncthreads();
    }
    int base = sb[0];
    for (int off = 1; off < 1024; off <<= 1) {
        int a = (t >= off) ? s[t - off] : 0;
        __syncthreads();
        s[t] += a;
        __syncthreads();
    }
    int incl = s[t];
    if (i < n) {
        g_rowptr[i] = base + incl - v;
        if (i == n - 1) g_rowptr[n] = base + incl;
    }
}

__global__ void csrfill_kernel(const int* __restrict__ src, const int* __restrict__ dst, int E) {
    int i = blockIdx.x * blockDim.x + threadIdx.x;
    if (i >= E) return;
    int d = dst[i];
    int sidx = src[i];
    int p = g_rowptr[d] + atomicAdd(&g_fill[d], 1);
    g_csr[p] = make_uint2((unsigned)sidx,
                          __float_as_uint(g_dinv[sidx] * g_dinv[d]));
}

// ---------------- fp16 mma helpers -------------------------------------------
__device__ __forceinline__ void ldmx4(uint32_t r[4], const __half* p) {
    uint32_t addr = (uint32_t)__cvta_generic_to_shared(p);
    asm volatile("ldmatrix.sync.aligned.m8n8.x4.shared.b16 {%0,%1,%2,%3}, [%4];"
        : "=r"(r[0]), "=r"(r[1]), "=r"(r[2]), "=r"(r[3]) : "r"(addr));
}
__device__ __forceinline__ void ldmx2(uint32_t r[2], const __half* p) {
    uint32_t addr = (uint32_t)__cvta_generic_to_shared(p);
    asm volatile("ldmatrix.sync.aligned.m8n8.x2.shared.b16 {%0,%1}, [%2];"
        : "=r"(r[0]), "=r"(r[1]) : "r"(addr));
}
__device__ __forceinline__ void mma_f16(float d[4], const uint32_t a[4], const uint32_t b[2]) {
    asm volatile("mma.sync.aligned.m16n8k16.row.col.f32.f16.f16.f32 "
        "{%0,%1,%2,%3}, {%4,%5,%6,%7}, {%8,%9}, {%0,%1,%2,%3};"
        : "+f"(d[0]), "+f"(d[1]), "+f"(d[2]), "+f"(d[3])
        : "r"(a[0]), "r"(a[1]), "r"(a[2]), "r"(a[3]), "r"(b[0]), "r"(b[1]));
}

// ---------------- fused GCN layer: gather-aggregate + fp16 MMA ----------------
// block = 512 threads; tile = 128 nodes (8/warp); H[128x128] = relu(Agg(X)*W + b)
// occupancy 3 blocks/SM (48 warps) for gather latency hiding
template <int DIN>
__global__ __launch_bounds__(512, 3)
void gcn_layer_kernel(const __half* __restrict__ X, const __half* __restrict__ WT,
                      const float* __restrict__ bias, __half* __restrict__ H, int M) {
    constexpr int AS = DIN + 8;          // half stride -> conflict-free ldmatrix
    constexpr int HPL = DIN / 32;        // halves per lane in gather (2 or 4)
    extern __shared__ __half smh[];
    __half* Asm = smh;                   // [128][AS]
    __half* Bsm = smh + 128 * AS;        // [128][AS] (n-major, k contiguous)
    int tid = threadIdx.x, warp = tid >> 5, lane = tid & 31;
    int m0 = blockIdx.x * 128;

    // ---- load W^T (fp16, [n][k]) into smem: 16B vector copies ----
    constexpr int V8 = DIN / 8;
    for (int i = tid; i < 128 * V8; i += 512) {
        int nr = i / V8;
        int kv = (i - nr * V8) * 8;
        *(uint4*)&Bsm[nr * AS + kv] = *(const uint4*)&WT[nr * DIN + kv];
    }

    // ---- phase A: gather-aggregate 8 nodes per warp (unroll-2) ----
    for (int i = 0; i < 8; i++) {
        int nl = warp * 8 + i;
        int node = m0 + nl;
        float acc0[HPL], acc1[HPL];
#pragma unroll
        for (int j = 0; j < HPL; j++) { acc0[j] = 0.f; acc1[j] = 0.f; }
        if (node < M) {
            float di = g_dinv[node];
            float w0 = 2.f * di * di;    // two self-loops
            const __half2* xb = (const __half2*)X;
            size_t rb = (size_t)node * (DIN / 2) + lane * (HPL / 2);
            if constexpr (HPL == 4) {
                uint2 u = *(const uint2*)(xb + rb);
                float2 f0 = __half22float2(*(__half2*)&u.x);
                float2 f1 = __half22float2(*(__half2*)&u.y);
                acc0[0] = w0 * f0.x; acc0[1] = w0 * f0.y;
                acc0[2] = w0 * f1.x; acc0[3] = w0 * f1.y;
            } else {
                float2 f0 = __half22float2(xb[rb]);
                acc0[0] = w0 * f0.x; acc0[1] = w0 * f0.y;
            }
            int e = g_rowptr[node], e1 = g_rowptr[node + 1];
            for (; e + 1 < e1; e += 2) {
                uint2 ed0 = g_csr[e], ed1 = g_csr[e + 1];
                float n0 = __uint_as_float(ed0.y);
                float n1 = __uint_as_float(ed1.y);
                size_t b0 = (size_t)ed0.x * (DIN / 2) + lane * (HPL / 2);
                size_t b1 = (size_t)ed1.x * (DIN / 2) + lane * (HPL / 2);
                if constexpr (HPL == 4) {
                    uint2 u0 = *(const uint2*)(xb + b0);
                    uint2 u1 = *(const uint2*)(xb + b1);
                    float2 a0 = __half22float2(*(__half2*)&u0.x);
                    float2 a1 = __half22float2(*(__half2*)&u0.y);
                    float2 c0 = __half22float2(*(__half2*)&u1.x);
                    float2 c1 = __half22float2(*(__half2*)&u1.y);
                    acc0[0] = fmaf(n0, a0.x, acc0[0]); acc0[1] = fmaf(n0, a0.y, acc0[1]);
                    acc0[2] = fmaf(n0, a1.x, acc0[2]); acc0[3] = fmaf(n0, a1.y, acc0[3]);
                    acc1[0] = fmaf(n1, c0.x, acc1[0]); acc1[1] = fmaf(n1, c0.y, acc1[1]);
                    acc1[2] = fmaf(n1, c1.x, acc1[2]); acc1[3] = fmaf(n1, c1.y, acc1[3]);
                } else {
                    float2 a0 = __half22float2(xb[b0]);
                    float2 c0 = __half22float2(xb[b1]);
                    acc0[0] = fmaf(n0, a0.x, acc0[0]); acc0[1] = fmaf(n0, a0.y, acc0[1]);
                    acc1[0] = fmaf(n1, c0.x, acc1[0]); acc1[1] = fmaf(n1, c0.y, acc1[1]);
                }
            }
            if (e < e1) {
                uint2 ed0 = g_csr[e];
                float n0 = __uint_as_float(ed0.y);
                size_t b0 = (size_t)ed0.x * (DIN / 2) + lane * (HPL / 2);
                if constexpr (HPL == 4) {
                    uint2 u0 = *(const uint2*)(xb + b0);
                    float2 a0 = __half22float2(*(__half2*)&u0.x);
                    float2 a1 = __half22float2(*(__half2*)&u0.y);
                    acc0[0] = fmaf(n0, a0.x, acc0[0]); acc0[1] = fmaf(n0, a0.y, acc0[1]);
                    acc0[2] = fmaf(n0, a1.x, acc0[2]); acc0[3] = fmaf(n0, a1.y, acc0[3]);
                } else {
                    float2 a0 = __half22float2(xb[b0]);
                    acc0[0] = fmaf(n0, a0.x, acc0[0]); acc0[1] = fmaf(n0, a0.y, acc0[1]);
                }
            }
        }
        if constexpr (HPL == 4) {
            __half2 h0 = __floats2half2_rn(acc0[0] + acc1[0], acc0[1] + acc1[1]);
            __half2 h1 = __floats2half2_rn(acc0[2] + acc1[2], acc0[3] + acc1[3]);
            uint2 pk;
            pk.x = *(uint32_t*)&h0; pk.y = *(uint32_t*)&h1;
            *(uint2*)&Asm[nl * AS + lane * 4] = pk;
        } else {
            __half2 h0 = __floats2half2_rn(acc0[0] + acc1[0], acc0[1] + acc1[1]);
            *(uint32_t*)&Asm[nl * AS + lane * 2] = *(uint32_t*)&h0;
        }
    }
    __syncthreads();

    // ---- phase B: fp16 MMA from smem, no barriers in k-loop ----
    int wm = (warp >> 2) * 32;
    int wn = (warp & 3) * 32;
    float acc[2][4][4];
#pragma unroll
    for (int mi = 0; mi < 2; mi++)
#pragma unroll
        for (int ni = 0; ni < 4; ni++)
#pragma unroll
            for (int r = 0; r < 4; r++) acc[mi][ni][r] = 0.f;

    int l16 = lane & 15;
#pragma unroll
    for (int kk = 0; kk < DIN; kk += 16) {
        uint32_t a[2][4];
#pragma unroll
        for (int mi = 0; mi < 2; mi++)
            ldmx4(a[mi], &Asm[(wm + mi * 16 + l16) * AS + kk + (lane >> 4) * 8]);
        uint32_t b[4][2];
#pragma unroll
        for (int ni = 0; ni < 4; ni++)
            ldmx2(b[ni], &Bsm[(wn + ni * 8 + (l16 & 7)) * AS + kk + (l16 >> 3) * 8]);
#pragma unroll
        for (int mi = 0; mi < 2; mi++)
#pragma unroll
            for (int ni = 0; ni < 4; ni++)
                mma_f16(acc[mi][ni], a[mi], b[ni]);
    }

    // ---- epilogue: bias + relu -> fp16 ----
    int ar = lane >> 2, ac = lane & 3;
#pragma unroll
    for (int mi = 0; mi < 2; mi++) {
        int row = m0 + wm + mi * 16 + ar;
#pragma unroll
        for (int ni = 0; ni < 4; ni++) {
            int col = wn + ni * 8 + 2 * ac;
            float2 bb = *(const float2*)(bias + col);
            if (row < M) {
                __half2 o = __floats2half2_rn(fmaxf(acc[mi][ni][0] + bb.x, 0.f),
                                              fmaxf(acc[mi][ni][1] + bb.y, 0.f));
                *(__half2*)(H + (size_t)row * 128 + col) = o;
            }
            if (row + 8 < M) {
                __half2 o = __floats2half2_rn(fmaxf(acc[mi][ni][2] + bb.x, 0.f),
                                              fmaxf(acc[mi][ni][3] + bb.y, 0.f));
                *(__half2*)(H + (size_t)(row + 8) * 128 + col) = o;
            }
        }
    }
}

// ---------------- pooling (segment bounds via binary search) ------------------
__device__ __forceinline__ int lbound(const int* __restrict__ b, int n, int v) {
    int lo = 0, hi = n;
    while (lo < hi) {
        int mid = (lo + hi) >> 1;
        if (b[mid] < v) lo = mid + 1; else hi = mid;
    }
    return lo;
}

__global__ void pool_kernel(const __half* __restrict__ h,
                            const int* __restrict__ batch, int n) {
    int g = blockIdx.x;
    int c = threadIdx.x;
    int s = lbound(batch, n, g);
    int e = lbound(batch, n, g + 1);
    float sum = 0.f, mx = 0.f;   // h >= 0 after relu
    for (int i = s; i < e; i++) {
        float v = __half2float(h[(size_t)i * 128 + c]);
        sum += v;
        mx = fmaxf(mx, v);
    }
    float cnt = (float)(e - s);
    if (cnt < 1.f) cnt = 1.f;
    g_xcat[g * 384 + c]       = sum / cnt;
    g_xcat[g * 384 + 128 + c] = mx;
}

// ---------------- tiled MLP: 16 rows/block, B streamed once per block ---------
template <int N>
__global__ void mlp_tiled(const float* __restrict__ A, int lda,
                          const float* __restrict__ B,
                          const float* __restrict__ bias,
                          float* __restrict__ C, int ldc,
                          int M, int K) {
    __shared__ float As[16][33];
    int n = threadIdx.x;
    int m0 = blockIdx.x * 16;
    float acc[16];
    float bv = bias[n];
#pragma unroll
    for (int r = 0; r < 16; r++) acc[r] = bv;

    for (int k0 = 0; k0 < K; k0 += 32) {
        for (int i = threadIdx.x; i < 16 * 32; i += N) {
            int r = i >> 5, kk = i & 31;
            int gm = m0 + r, gk = k0 + kk;
            As[r][kk] = (gm < M && gk < K) ? A[(size_t)gm * lda + gk] : 0.f;
        }
        __syncthreads();
        int kmax = (K - k0 < 32) ? (K - k0) : 32;
        for (int kk = 0; kk < kmax; kk++) {
            float b = B[(size_t)(k0 + kk) * N + n];
#pragma unroll
            for (int r = 0; r < 16; r++)
                acc[r] = fmaf(As[r][kk], b, acc[r]);
        }
        __syncthreads();
    }
#pragma unroll
    for (int r = 0; r < 16; r++) {
        int gm = m0 + r;
        if (gm < M) C[(size_t)gm * ldc + n] = fmaxf(acc[r], 0.f);
    }
}

__global__ void final_kernel(const float* __restrict__ A, const float* __restrict__ W,
                             const float* __restrict__ b, float* __restrict__ out, int M) {
    int gw   = (blockIdx.x * blockDim.x + threadIdx.x) >> 5;
    int lane = threadIdx.x & 31;
    if (gw >= M) return;
    float s = 0.f;
    for (int k = lane; k < 128; k += 32)
        s = fmaf(A[(size_t)gw * 128 + k], W[k], s);
    for (int o = 16; o; o >>= 1) s += __shfl_xor_sync(0xffffffffu, s, o);
    if (lane == 0) out[gw] = 1.f / (1.f + expf(-(s + b[0])));
}

// ---------------- launch ------------------------------------------------------
extern "C" void kernel_launch(void* const* d_in, const int* in_sizes, int n_in,
                              void* d_out, int out_size) {
    const float* x_graph = (const float*)d_in[0];
    const int*   ei      = (const int*)d_in[1];
    const int*   batch   = (const int*)d_in[2];
    const float* x_tab   = (const float*)d_in[3];
    const float* Wg1 = (const float*)d_in[4];  const float* bg1 = (const float*)d_in[5];
    const float* Wg2 = (const float*)d_in[6];  const float* bg2 = (const float*)d_in[7];
    const float* Wg3 = (const float*)d_in[8];  const float* bg3 = (const float*)d_in[9];
    const float* Wg4 = (const float*)d_in[10]; const float* bg4 = (const float*)d_in[11];
    const float* Wt1 = (const float*)d_in[12]; const float* bt1 = (const float*)d_in[13];
    const float* Wt2 = (const float*)d_in[14]; const float* bt2 = (const float*)d_in[15];
    const float* Wf1 = (const float*)d_in[16]; const float* bf1 = (const float*)d_in[17];
    const float* Wf2 = (const float*)d_in[18]; const float* bf2 = (const float*)d_in[19];
    const float* Wf3 = (const float*)d_in[20]; const float* bf3 = (const float*)d_in[21];
    float* out = (float*)d_out;

    int n  = in_sizes[0] / 64;    // nodes
    int E  = in_sizes[1] / 2;     // edges
    int nb = in_sizes[3] / 200;   // graphs

    const int* src = ei;
    const int* dst = ei + E;

    __half *xhp, *hap, *hbp, *wt1p, *wt2p, *wt3p, *wt4p;
    float *xcatp, *t1p, *f1p, *f2p;
    cudaGetSymbolAddress((void**)&xhp,   g_xh);
    cudaGetSymbolAddress((void**)&hap,   g_ha);
    cudaGetSymbolAddress((void**)&hbp,   g_hb);
    cudaGetSymbolAddress((void**)&wt1p,  g_wt1);
    cudaGetSymbolAddress((void**)&wt2p,  g_wt2);
    cudaGetSymbolAddress((void**)&wt3p,  g_wt3);
    cudaGetSymbolAddress((void**)&wt4p,  g_wt4);
    cudaGetSymbolAddress((void**)&xcatp, g_xcat);
    cudaGetSymbolAddress((void**)&t1p,   g_t1);
    cudaGetSymbolAddress((void**)&f1p,   g_f1);
    cudaGetSymbolAddress((void**)&f2p,   g_f2);

    // dynamic smem: 2 x 128 rows x (DIN+8) halves
    int smem128 = 2 * 128 * (128 + 8) * 2;   // 69,632 B
    int smem64  = 2 * 128 * (64 + 8) * 2;    // 36,864 B
    cudaFuncSetAttribute(gcn_layer_kernel<128>, cudaFuncAttributeMaxDynamicSharedMemorySize, smem128);
    cudaFuncSetAttribute(gcn_layer_kernel<64>,  cudaFuncAttributeMaxDynamicSharedMemorySize, smem64);

    int tb = 256;
    int nBlocksE = (E + tb - 1) / tb;
    int nsb = (n + 1023) / 1024;
    int layerBlocks = (n + 127) / 128;
    int mlpBlocks = (nb + 15) / 16;

    // ---- prep + degree/CSR ----
    prep_kernel<<<(n * 64 + tb - 1) / tb, tb>>>(x_graph, n, Wg1, Wg2, Wg3, Wg4);
    hist_kernel<<<nBlocksE, tb>>>(dst, E);
    scan1_kernel<<<nsb, 1024>>>(n);
    scan23_kernel<<<nsb, 1024>>>(n, nsb);
    csrfill_kernel<<<nBlocksE, tb>>>(src, dst, E);

    // ---- fused GCN layers ----
    gcn_layer_kernel<64><<<layerBlocks, 512, smem64>>>(xhp, wt1p, bg1, hap, n);
    gcn_layer_kernel<128><<<layerBlocks, 512, smem128>>>(hap, wt2p, bg2, hbp, n);
    gcn_layer_kernel<128><<<layerBlocks, 512, smem128>>>(hbp, wt3p, bg3, hap, n);
    gcn_layer_kernel<128><<<layerBlocks, 512, smem128>>>(hap, wt4p, bg4, hbp, n);

    // ---- pooling (binary-search segments) ----
    pool_kernel<<<nb, 128>>>(hbp, batch, n);

    // ---- tabular branch (tiled MLPs) ----
    mlp_tiled<256><<<mlpBlocks, 256>>>(x_tab, 200, Wt1, bt1, t1p, 256, nb, 200);
    mlp_tiled<128><<<mlpBlocks, 128>>>(t1p, 256, Wt2, bt2, xcatp + 256, 384, nb, 256);

    // ---- fused head ----
    mlp_tiled<256><<<mlpBlocks, 256>>>(xcatp, 384, Wf1, bf1, f1p, 256, nb, 384);
    mlp_tiled<128><<<mlpBlocks, 128>>>(f1p, 256, Wf2, bf2, f2p, 128, nb, 256);
    final_kernel<<<(nb * 32 + tb - 1) / tb, tb>>>(f2p, Wf3, bf3, out, nb);
}

// round 15
// speedup vs baseline: 1.3381x; 1.1449x over previous
#include <cuda_runtime.h>
#include <cuda_fp16.h>
#include <stdint.h>
#include <math.h>

#define MAXN 100000
#define MAXE 1600000
#define MAXB 1024

// ---------------- scratch (static device globals; no allocation) -------------
__device__ int    g_deg[MAXN];
__device__ float  g_dinv[MAXN];
__device__ int    g_rowptr[MAXN + 1];
__device__ int    g_fill[MAXN];
__device__ uint2  g_csr[MAXE];                 // packed {src, norm_bits}
__device__ __half g_xh[(size_t)MAXN * 64];     // fp16 input features
__device__ __half g_ha[(size_t)MAXN * 128];    // fp16 hidden ping
__device__ __half g_hb[(size_t)MAXN * 128];    // fp16 hidden pong
__device__ __half g_agg16[(size_t)MAXN * 128]; // fp16 aggregated features
__device__ __half g_wt1[64 * 128];             // W1^T fp16 [n][k]
__device__ __half g_wt2[128 * 128];
__device__ __half g_wt3[128 * 128];
__device__ __half g_wt4[128 * 128];
__device__ int    g_bsum[1024];
__device__ float  g_xcat[MAXB * 384];
__device__ float  g_t1[MAXB * 256];
__device__ float  g_f1[MAXB * 256];
__device__ float  g_f2[MAXB * 128];

// ---------------- prep: x->fp16, W->fp16 transposed, zero deg/fill -----------
__global__ void prep_kernel(const float* __restrict__ x, int n,
                            const float* __restrict__ W1, const float* __restrict__ W2,
                            const float* __restrict__ W3, const float* __restrict__ W4) {
    int i = blockIdx.x * blockDim.x + threadIdx.x;
    int total = n * 64;
    if (i < total) g_xh[i] = __float2half(x[i]);
    if (i < n) { g_deg[i] = 0; g_fill[i] = 0; }
    if (i < 8192) {                       // W1: K=64
        int nr = i >> 6, k = i & 63;
        g_wt1[nr * 64 + k] = __float2half(W1[k * 128 + nr]);
    } else if (i < 8192 + 16384) {
        int j = i - 8192; int nr = j >> 7, k = j & 127;
        g_wt2[nr * 128 + k] = __float2half(W2[k * 128 + nr]);
    } else if (i < 8192 + 2 * 16384) {
        int j = i - 8192 - 16384; int nr = j >> 7, k = j & 127;
        g_wt3[nr * 128 + k] = __float2half(W3[k * 128 + nr]);
    } else if (i < 8192 + 3 * 16384) {
        int j = i - 8192 - 2 * 16384; int nr = j >> 7, k = j & 127;
        g_wt4[nr * 128 + k] = __float2half(W4[k * 128 + nr]);
    }
}

__global__ void hist_kernel(const int* __restrict__ dst, int E) {
    int i = blockIdx.x * blockDim.x + threadIdx.x;
    if (i < E) atomicAdd(&g_deg[dst[i]], 1);
}

// block sums of deg (1024 per block) + fused dinv
__global__ void scan1_kernel(int n) {
    __shared__ int s[1024];
    int t = threadIdx.x;
    int i = blockIdx.x * 1024 + t;
    int v = (i < n) ? g_deg[i] : 0;
    if (i < n) g_dinv[i] = rsqrtf((float)(v + 2));
    s[t] = v;
    __syncthreads();
    for (int off = 512; off > 0; off >>= 1) {
        if (t < off) s[t] += s[t + off];
        __syncthreads();
    }
    if (t == 0) g_bsum[blockIdx.x] = s[0];
}

// merged scan2+scan3: each block redundantly reduces bsum[0..blk) for its base
__global__ void scan23_kernel(int n, int nsb) {
    __shared__ int s[1024];
    __shared__ int sb[1024];
    int t = threadIdx.x;
    int i = blockIdx.x * 1024 + t;
    sb[t] = (t < blockIdx.x) ? g_bsum[t] : 0;
    int v = (i < n) ? g_deg[i] : 0;
    s[t] = v;
    __syncthreads();
    for (int off = 512; off > 0; off >>= 1) {
        if (t < off) sb[t] += sb[t + off];
        __syncthreads();
    }
    int base = sb[0];
    for (int off = 1; off < 1024; off <<= 1) {
        int a = (t >= off) ? s[t - off] : 0;
        __syncthreads();
        s[t] += a;
        __syncthreads();
    }
    int incl = s[t];
    if (i < n) {
        g_rowptr[i] = base + incl - v;
        if (i == n - 1) g_rowptr[n] = base + incl;
    }
}

__global__ void csrfill_kernel(const int* __restrict__ src, const int* __restrict__ dst, int E) {
    int i = blockIdx.x * blockDim.x + threadIdx.x;
    if (i >= E) return;
    int d = dst[i];
    int sidx = src[i];
    int p = g_rowptr[d] + atomicAdd(&g_fill[d], 1);
    g_csr[p] = make_uint2((unsigned)sidx,
                          __float_as_uint(g_dinv[sidx] * g_dinv[d]));
}

// ---------------- standalone aggregation: one warp per node, high occupancy ---
template <int DIN>
__global__ __launch_bounds__(256)
void agg_kernel(const __half* __restrict__ X, __half* __restrict__ OUT, int M) {
    constexpr int HPL = DIN / 32;        // halves per lane (2 or 4)
    int gw   = (blockIdx.x * blockDim.x + threadIdx.x) >> 5;
    int lane = threadIdx.x & 31;
    if (gw >= M) return;
    int node = gw;
    float acc0[HPL], acc1[HPL];
#pragma unroll
    for (int j = 0; j < HPL; j++) { acc0[j] = 0.f; acc1[j] = 0.f; }
    float di = g_dinv[node];
    float w0 = 2.f * di * di;            // two self-loops
    const __half2* xb = (const __half2*)X;
    size_t rb = (size_t)node * (DIN / 2) + lane * (HPL / 2);
    if constexpr (HPL == 4) {
        uint2 u = *(const uint2*)(xb + rb);
        float2 f0 = __half22float2(*(__half2*)&u.x);
        float2 f1 = __half22float2(*(__half2*)&u.y);
        acc0[0] = w0 * f0.x; acc0[1] = w0 * f0.y;
        acc0[2] = w0 * f1.x; acc0[3] = w0 * f1.y;
    } else {
        float2 f0 = __half22float2(xb[rb]);
        acc0[0] = w0 * f0.x; acc0[1] = w0 * f0.y;
    }
    int e = g_rowptr[node], e1 = g_rowptr[node + 1];
    for (; e + 1 < e1; e += 2) {
        uint2 ed0 = g_csr[e], ed1 = g_csr[e + 1];
        float n0 = __uint_as_float(ed0.y);
        float n1 = __uint_as_float(ed1.y);
        size_t b0 = (size_t)ed0.x * (DIN / 2) + lane * (HPL / 2);
        size_t b1 = (size_t)ed1.x * (DIN / 2) + lane * (HPL / 2);
        if constexpr (HPL == 4) {
            uint2 u0 = *(const uint2*)(xb + b0);
            uint2 u1 = *(const uint2*)(xb + b1);
            float2 a0 = __half22float2(*(__half2*)&u0.x);
            float2 a1 = __half22float2(*(__half2*)&u0.y);
            float2 c0 = __half22float2(*(__half2*)&u1.x);
            float2 c1 = __half22float2(*(__half2*)&u1.y);
            acc0[0] = fmaf(n0, a0.x, acc0[0]); acc0[1] = fmaf(n0, a0.y, acc0[1]);
            acc0[2] = fmaf(n0, a1.x, acc0[2]); acc0[3] = fmaf(n0, a1.y, acc0[3]);
            acc1[0] = fmaf(n1, c0.x, acc1[0]); acc1[1] = fmaf(n1, c0.y, acc1[1]);
            acc1[2] = fmaf(n1, c1.x, acc1[2]); acc1[3] = fmaf(n1, c1.y, acc1[3]);
        } else {
            float2 a0 = __half22float2(xb[b0]);
            float2 c0 = __half22float2(xb[b1]);
            acc0[0] = fmaf(n0, a0.x, acc0[0]); acc0[1] = fmaf(n0, a0.y, acc0[1]);
            acc1[0] = fmaf(n1, c0.x, acc1[0]); acc1[1] = fmaf(n1, c0.y, acc1[1]);
        }
    }
    if (e < e1) {
        uint2 ed0 = g_csr[e];
        float n0 = __uint_as_float(ed0.y);
        size_t b0 = (size_t)ed0.x * (DIN / 2) + lane * (HPL / 2);
        if constexpr (HPL == 4) {
            uint2 u0 = *(const uint2*)(xb + b0);
            float2 a0 = __half22float2(*(__half2*)&u0.x);
            float2 a1 = __half22float2(*(__half2*)&u0.y);
            acc0[0] = fmaf(n0, a0.x, acc0[0]); acc0[1] = fmaf(n0, a0.y, acc0[1]);
            acc0[2] = fmaf(n0, a1.x, acc0[2]); acc0[3] = fmaf(n0, a1.y, acc0[3]);
        } else {
            float2 a0 = __half22float2(xb[b0]);
            acc0[0] = fmaf(n0, a0.x, acc0[0]); acc0[1] = fmaf(n0, a0.y, acc0[1]);
        }
    }
    if constexpr (HPL == 4) {
        __half2 h0 = __floats2half2_rn(acc0[0] + acc1[0], acc0[1] + acc1[1]);
        __half2 h1 = __floats2half2_rn(acc0[2] + acc1[2], acc0[3] + acc1[3]);
        uint2 pk;
        pk.x = *(uint32_t*)&h0; pk.y = *(uint32_t*)&h1;
        *(uint2*)&OUT[(size_t)node * DIN + lane * 4] = pk;
    } else {
        __half2 h0 = __floats2half2_rn(acc0[0] + acc1[0], acc0[1] + acc1[1]);
        *(uint32_t*)&OUT[(size_t)node * DIN + lane * 2] = *(uint32_t*)&h0;
    }
}

// ---------------- fp16 mma helpers -------------------------------------------
__device__ __forceinline__ void ldmx4(uint32_t r[4], const __half* p) {
    uint32_t addr = (uint32_t)__cvta_generic_to_shared(p);
    asm volatile("ldmatrix.sync.aligned.m8n8.x4.shared.b16 {%0,%1,%2,%3}, [%4];"
        : "=r"(r[0]), "=r"(r[1]), "=r"(r[2]), "=r"(r[3]) : "r"(addr));
}
__device__ __forceinline__ void ldmx2(uint32_t r[2], const __half* p) {
    uint32_t addr = (uint32_t)__cvta_generic_to_shared(p);
    asm volatile("ldmatrix.sync.aligned.m8n8.x2.shared.b16 {%0,%1}, [%2];"
        : "=r"(r[0]), "=r"(r[1]) : "r"(addr));
}
__device__ __forceinline__ void mma_f16(float d[4], const uint32_t a[4], const uint32_t b[2]) {
    asm volatile("mma.sync.aligned.m16n8k16.row.col.f32.f16.f16.f32 "
        "{%0,%1,%2,%3}, {%4,%5,%6,%7}, {%8,%9}, {%0,%1,%2,%3};"
        : "+f"(d[0]), "+f"(d[1]), "+f"(d[2]), "+f"(d[3])
        : "r"(a[0]), "r"(a[1]), "r"(a[2]), "r"(a[3]), "r"(b[0]), "r"(b[1]));
}

// ---------------- GEMM layer: H[128x128] = relu(AGG[128xDIN]*W + b), fp16 MMA -
template <int DIN>
__global__ __launch_bounds__(512, 2)
void gemm_kernel(const __half* __restrict__ G, const __half* __restrict__ WT,
                 const float* __restrict__ bias, __half* __restrict__ H, int M) {
    constexpr int AS = DIN + 8;          // half stride -> conflict-free ldmatrix
    extern __shared__ __half smh[];
    __half* Asm = smh;                   // [128][AS]
    __half* Bsm = smh + 128 * AS;        // [128][AS] (n-major, k contiguous)
    int tid = threadIdx.x, warp = tid >> 5, lane = tid & 31;
    int m0 = blockIdx.x * 128;

    // load W^T and A tile (both coalesced 16B vectors)
    constexpr int V8 = DIN / 8;
    for (int i = tid; i < 128 * V8; i += 512) {
        int nr = i / V8;
        int kv = (i - nr * V8) * 8;
        *(uint4*)&Bsm[nr * AS + kv] = *(const uint4*)&WT[nr * DIN + kv];
        int gm = m0 + nr;
        uint4 av = make_uint4(0u, 0u, 0u, 0u);
        if (gm < M) av = *(const uint4*)&G[(size_t)gm * DIN + kv];
        *(uint4*)&Asm[nr * AS + kv] = av;
    }
    __syncthreads();

    // fp16 MMA, no barriers in k-loop
    int wm = (warp >> 2) * 32;
    int wn = (warp & 3) * 32;
    float acc[2][4][4];
#pragma unroll
    for (int mi = 0; mi < 2; mi++)
#pragma unroll
        for (int ni = 0; ni < 4; ni++)
#pragma unroll
            for (int r = 0; r < 4; r++) acc[mi][ni][r] = 0.f;

    int l16 = lane & 15;
#pragma unroll
    for (int kk = 0; kk < DIN; kk += 16) {
        uint32_t a[2][4];
#pragma unroll
        for (int mi = 0; mi < 2; mi++)
            ldmx4(a[mi], &Asm[(wm + mi * 16 + l16) * AS + kk + (lane >> 4) * 8]);
        uint32_t b[4][2];
#pragma unroll
        for (int ni = 0; ni < 4; ni++)
            ldmx2(b[ni], &Bsm[(wn + ni * 8 + (l16 & 7)) * AS + kk + (l16 >> 3) * 8]);
#pragma unroll
        for (int mi = 0; mi < 2; mi++)
#pragma unroll
            for (int ni = 0; ni < 4; ni++)
                mma_f16(acc[mi][ni], a[mi], b[ni]);
    }

    // epilogue: bias + relu -> fp16
    int ar = lane >> 2, ac = lane & 3;
#pragma unroll
    for (int mi = 0; mi < 2; mi++) {
        int row = m0 + wm + mi * 16 + ar;
#pragma unroll
        for (int ni = 0; ni < 4; ni++) {
            int col = wn + ni * 8 + 2 * ac;
            float2 bb = *(const float2*)(bias + col);
            if (row < M) {
                __half2 o = __floats2half2_rn(fmaxf(acc[mi][ni][0] + bb.x, 0.f),
                                              fmaxf(acc[mi][ni][1] + bb.y, 0.f));
                *(__half2*)(H + (size_t)row * 128 + col) = o;
            }
            if (row + 8 < M) {
                __half2 o = __floats2half2_rn(fmaxf(acc[mi][ni][2] + bb.x, 0.f),
                                              fmaxf(acc[mi][ni][3] + bb.y, 0.f));
                *(__half2*)(H + (size_t)(row + 8) * 128 + col) = o;
            }
        }
    }
}

// ---------------- pooling (segment bounds via binary search) ------------------
__device__ __forceinline__ int lbound(const int* __restrict__ b, int n, int v) {
    int lo = 0, hi = n;
    while (lo < hi) {
        int mid = (lo + hi) >> 1;
        if (b[mid] < v) lo = mid + 1; else hi = mid;
    }
    return lo;
}

__global__ void pool_kernel(const __half* __restrict__ h,
                            const int* __restrict__ batch, int n) {
    int g = blockIdx.x;
    int c = threadIdx.x;
    int s = lbound(batch, n, g);
    int e = lbound(batch, n, g + 1);
    float sum = 0.f, mx = 0.f;   // h >= 0 after relu
    for (int i = s; i < e; i++) {
        float v = __half2float(h[(size_t)i * 128 + c]);
        sum += v;
        mx = fmaxf(mx, v);
    }
    float cnt = (float)(e - s);
    if (cnt < 1.f) cnt = 1.f;
    g_xcat[g * 384 + c]       = sum / cnt;
    g_xcat[g * 384 + 128 + c] = mx;
}

// ---------------- tiled MLP: 16 rows/block, B streamed once per block ---------
template <int N>
__global__ void mlp_tiled(const float* __restrict__ A, int lda,
                          const float* __restrict__ B,
                          const float* __restrict__ bias,
                          float* __restrict__ C, int ldc,
                          int M, int K) {
    __shared__ float As[16][33];
    int n = threadIdx.x;
    int m0 = blockIdx.x * 16;
    float acc[16];
    float bv = bias[n];
#pragma unroll
    for (int r = 0; r < 16; r++) acc[r] = bv;

    for (int k0 = 0; k0 < K; k0 += 32) {
        for (int i = threadIdx.x; i < 16 * 32; i += N) {
            int r = i >> 5, kk = i & 31;
            int gm = m0 + r, gk = k0 + kk;
            As[r][kk] = (gm < M && gk < K) ? A[(size_t)gm * lda + gk] : 0.f;
        }
        __syncthreads();
        int kmax = (K - k0 < 32) ? (K - k0) : 32;
        for (int kk = 0; kk < kmax; kk++) {
            float b = B[(size_t)(k0 + kk) * N + n];
#pragma unroll
            for (int r = 0; r < 16; r++)
                acc[r] = fmaf(As[r][kk], b, acc[r]);
        }
        __syncthreads();
    }
#pragma unroll
    for (int r = 0; r < 16; r++) {
        int gm = m0 + r;
        if (gm < M) C[(size_t)gm * ldc + n] = fmaxf(acc[r], 0.f);
    }
}

__global__ void final_kernel(const float* __restrict__ A, const float* __restrict__ W,
                             const float* __restrict__ b, float* __restrict__ out, int M) {
    int gw   = (blockIdx.x * blockDim.x + threadIdx.x) >> 5;
    int lane = threadIdx.x & 31;
    if (gw >= M) return;
    float s = 0.f;
    for (int k = lane; k < 128; k += 32)
        s = fmaf(A[(size_t)gw * 128 + k], W[k], s);
    for (int o = 16; o; o >>= 1) s += __shfl_xor_sync(0xffffffffu, s, o);
    if (lane == 0) out[gw] = 1.f / (1.f + expf(-(s + b[0])));
}

// ---------------- launch ------------------------------------------------------
extern "C" void kernel_launch(void* const* d_in, const int* in_sizes, int n_in,
                              void* d_out, int out_size) {
    const float* x_graph = (const float*)d_in[0];
    const int*   ei      = (const int*)d_in[1];
    const int*   batch   = (const int*)d_in[2];
    const float* x_tab   = (const float*)d_in[3];
    const float* Wg1 = (const float*)d_in[4];  const float* bg1 = (const float*)d_in[5];
    const float* Wg2 = (const float*)d_in[6];  const float* bg2 = (const float*)d_in[7];
    const float* Wg3 = (const float*)d_in[8];  const float* bg3 = (const float*)d_in[9];
    const float* Wg4 = (const float*)d_in[10]; const float* bg4 = (const float*)d_in[11];
    const float* Wt1 = (const float*)d_in[12]; const float* bt1 = (const float*)d_in[13];
    const float* Wt2 = (const float*)d_in[14]; const float* bt2 = (const float*)d_in[15];
    const float* Wf1 = (const float*)d_in[16]; const float* bf1 = (const float*)d_in[17];
    const float* Wf2 = (const float*)d_in[18]; const float* bf2 = (const float*)d_in[19];
    const float* Wf3 = (const float*)d_in[20]; const float* bf3 = (const float*)d_in[21];
    float* out = (float*)d_out;

    int n  = in_sizes[0] / 64;    // nodes
    int E  = in_sizes[1] / 2;     // edges
    int nb = in_sizes[3] / 200;   // graphs

    const int* src = ei;
    const int* dst = ei + E;

    __half *xhp, *hap, *hbp, *aggp, *wt1p, *wt2p, *wt3p, *wt4p;
    float *xcatp, *t1p, *f1p, *f2p;
    cudaGetSymbolAddress((void**)&xhp,   g_xh);
    cudaGetSymbolAddress((void**)&hap,   g_ha);
    cudaGetSymbolAddress((void**)&hbp,   g_hb);
    cudaGetSymbolAddress((void**)&aggp,  g_agg16);
    cudaGetSymbolAddress((void**)&wt1p,  g_wt1);
    cudaGetSymbolAddress((void**)&wt2p,  g_wt2);
    cudaGetSymbolAddress((void**)&wt3p,  g_wt3);
    cudaGetSymbolAddress((void**)&wt4p,  g_wt4);
    cudaGetSymbolAddress((void**)&xcatp, g_xcat);
    cudaGetSymbolAddress((void**)&t1p,   g_t1);
    cudaGetSymbolAddress((void**)&f1p,   g_f1);
    cudaGetSymbolAddress((void**)&f2p,   g_f2);

    // dynamic smem: 2 x 128 rows x (DIN+8) halves
    int smem128 = 2 * 128 * (128 + 8) * 2;   // 69,632 B
    int smem64  = 2 * 128 * (64 + 8) * 2;    // 36,864 B
    cudaFuncSetAttribute(gemm_kernel<128>, cudaFuncAttributeMaxDynamicSharedMemorySize, smem128);
    cudaFuncSetAttribute(gemm_kernel<64>,  cudaFuncAttributeMaxDynamicSharedMemorySize, smem64);

    int tb = 256;
    int nBlocksE = (E + tb - 1) / tb;
    int nsb = (n + 1023) / 1024;
    int aggBlocks  = (n + 7) / 8;            // one warp per node, 8 warps/block
    int gemmBlocks = (n + 127) / 128;
    int mlpBlocks = (nb + 15) / 16;

    // ---- prep + degree/CSR ----
    prep_kernel<<<(n * 64 + tb - 1) / tb, tb>>>(x_graph, n, Wg1, Wg2, Wg3, Wg4);
    hist_kernel<<<nBlocksE, tb>>>(dst, E);
    scan1_kernel<<<nsb, 1024>>>(n);
    scan23_kernel<<<nsb, 1024>>>(n, nsb);
    csrfill_kernel<<<nBlocksE, tb>>>(src, dst, E);

    // ---- GCN layers: high-occupancy agg + MMA gemm ----
    agg_kernel<64><<<aggBlocks, tb>>>(xhp, aggp, n);
    gemm_kernel<64><<<gemmBlocks, 512, smem64>>>(aggp, wt1p, bg1, hap, n);
    agg_kernel<128><<<aggBlocks, tb>>>(hap, aggp, n);
    gemm_kernel<128><<<gemmBlocks, 512, smem128>>>(aggp, wt2p, bg2, hbp, n);
    agg_kernel<128><<<aggBlocks, tb>>>(hbp, aggp, n);
    gemm_kernel<128><<<gemmBlocks, 512, smem128>>>(aggp, wt3p, bg3, hap, n);
    agg_kernel<128><<<aggBlocks, tb>>>(hap, aggp, n);
    gemm_kernel<128><<<gemmBlocks, 512, smem128>>>(aggp, wt4p, bg4, hbp, n);

    // ---- pooling (binary-search segments) ----
    pool_kernel<<<nb, 128>>>(hbp, batch, n);

    // ---- tabular branch (tiled MLPs) ----
    mlp_tiled<256><<<mlpBlocks, 256>>>(x_tab, 200, Wt1, bt1, t1p, 256, nb, 200);
    mlp_tiled<128><<<mlpBlocks, 128>>>(t1p, 256, Wt2, bt2, xcatp + 256, 384, nb, 256);

    // ---- fused head ----
    mlp_tiled<256><<<mlpBlocks, 256>>>(xcatp, 384, Wf1, bf1, f1p, 256, nb, 384);
    mlp_tiled<128><<<mlpBlocks, 128>>>(f1p, 256, Wf2, bf2, f2p, 128, nb, 256);
    final_kernel<<<(nb * 32 + tb - 1) / tb, tb>>>(f2p, Wf3, bf3, out, nb);
}